// round 1
// baseline (speedup 1.0000x reference)
#include <cuda_runtime.h>
#include <cuda_bf16.h>

// Problem constants
#define Bb 2
#define Tt 2048
#define Dd 1024
#define Hh 16
#define HDd 64
#define M_ROWS (Bb * Tt)        // 4096

// Scratch (allocation-free rule: device globals)
__device__ float g_qkv[(size_t)M_ROWS * 3 * Dd];   // (4096, 3072)
__device__ float g_attn[(size_t)M_ROWS * Dd];      // (4096, 1024)

// ---------------------------------------------------------------------------
// SGEMM: C[M,N] = A[M,K] @ B[K,N], all row-major, M%128==0, N%128==0, K%16==0
// 128x128 block, BK=16, 256 threads, 8x8 per-thread microtile.
// ---------------------------------------------------------------------------
__global__ __launch_bounds__(256) void sgemm128(
    const float* __restrict__ A, const float* __restrict__ B,
    float* __restrict__ C, int M, int N, int K)
{
    __shared__ float Ast[16][128];   // A tile transposed: [k][row]
    __shared__ float Bs[16][128];    // B tile natural:   [k][col]

    const int tid = threadIdx.x;
    const int tx = tid & 15;         // 0..15 -> col group
    const int ty = tid >> 4;         // 0..15 -> row group
    const int brow = blockIdx.y * 128;
    const int bcol = blockIdx.x * 128;

    float acc[8][8] = {};

    // float4 tile-load ids (512 float4 per tile, 2 per thread)
    const int aq0 = tid, aq1 = tid + 256;
    const int bq0 = tid, bq1 = tid + 256;

    for (int kt = 0; kt < K; kt += 16) {
        // global loads into registers
        const int ar0 = aq0 >> 2, ac0 = (aq0 & 3) * 4;
        const int ar1 = aq1 >> 2, ac1 = (aq1 & 3) * 4;
        float4 a0 = *(const float4*)&A[(size_t)(brow + ar0) * K + kt + ac0];
        float4 a1 = *(const float4*)&A[(size_t)(brow + ar1) * K + kt + ac1];
        const int br0 = bq0 >> 5, bc0 = (bq0 & 31) * 4;
        const int br1 = bq1 >> 5, bc1 = (bq1 & 31) * 4;
        float4 b0 = *(const float4*)&B[(size_t)(kt + br0) * N + bcol + bc0];
        float4 b1 = *(const float4*)&B[(size_t)(kt + br1) * N + bcol + bc1];

        __syncthreads();  // previous compute done before overwriting smem

        Ast[ac0 + 0][ar0] = a0.x; Ast[ac0 + 1][ar0] = a0.y;
        Ast[ac0 + 2][ar0] = a0.z; Ast[ac0 + 3][ar0] = a0.w;
        Ast[ac1 + 0][ar1] = a1.x; Ast[ac1 + 1][ar1] = a1.y;
        Ast[ac1 + 2][ar1] = a1.z; Ast[ac1 + 3][ar1] = a1.w;
        *(float4*)&Bs[br0][bc0] = b0;
        *(float4*)&Bs[br1][bc1] = b1;

        __syncthreads();

        #pragma unroll
        for (int kk = 0; kk < 16; kk++) {
            float4 af0 = *(const float4*)&Ast[kk][ty * 8];
            float4 af1 = *(const float4*)&Ast[kk][ty * 8 + 4];
            float4 bf0 = *(const float4*)&Bs[kk][tx * 8];
            float4 bf1 = *(const float4*)&Bs[kk][tx * 8 + 4];
            float ar[8] = {af0.x, af0.y, af0.z, af0.w, af1.x, af1.y, af1.z, af1.w};
            float br[8] = {bf0.x, bf0.y, bf0.z, bf0.w, bf1.x, bf1.y, bf1.z, bf1.w};
            #pragma unroll
            for (int i = 0; i < 8; i++)
                #pragma unroll
                for (int j = 0; j < 8; j++)
                    acc[i][j] += ar[i] * br[j];
        }
    }

    #pragma unroll
    for (int i = 0; i < 8; i++) {
        float* crow = &C[(size_t)(brow + ty * 8 + i) * N + bcol + tx * 8];
        *(float4*)&crow[0] = make_float4(acc[i][0], acc[i][1], acc[i][2], acc[i][3]);
        *(float4*)&crow[4] = make_float4(acc[i][4], acc[i][5], acc[i][6], acc[i][7]);
    }
}

// ---------------------------------------------------------------------------
// RoPE applied in-place to Q and K halves of the qkv buffer.
// rope layout: (T, 32, 2) -> [cos, sin]
// ---------------------------------------------------------------------------
__global__ void rope_kernel(float* __restrict__ qkv, const float* __restrict__ rope)
{
    int idx = blockIdx.x * blockDim.x + threadIdx.x;  // over B*T*H*32
    int i = idx & 31;
    int h = (idx >> 5) & 15;
    int t = (idx >> 9) & (Tt - 1);
    int b = idx >> 20;  // 32*16*2048 = 2^20

    float c = rope[(t * 32 + i) * 2 + 0];
    float s = rope[(t * 32 + i) * 2 + 1];
    size_t base = ((size_t)(b * Tt + t)) * 3072 + h * 64 + 2 * i;

    float x0 = qkv[base], x1 = qkv[base + 1];
    qkv[base]     = x0 * c - x1 * s;
    qkv[base + 1] = x1 * c + x0 * s;

    float y0 = qkv[base + 1024], y1 = qkv[base + 1025];
    qkv[base + 1024] = y0 * c - y1 * s;
    qkv[base + 1025] = y1 * c + y0 * s;
}

// ---------------------------------------------------------------------------
// Flash attention: causal, per-(b,h), BM=BN=64, HD=64, 256 threads.
// Each thread owns a 4x4 S microtile (rows ty*4.., cols tx*4..) and a 4x4
// O microtile (rows ty*4.., dims tx*4..). Row stats via width-16 shuffles.
// ---------------------------------------------------------------------------
#define ATTN_SMEM_BYTES ((64 * 68 * 2 + 64 * 64 * 2) * 4)   // 67584

__global__ __launch_bounds__(256) void attn_kernel(
    const float* __restrict__ qkv, float* __restrict__ out)
{
    extern __shared__ float sm[];
    float* Qt = sm;                 // [64 k][68 pad] transposed, pre-scaled
    float* Kt = Qt + 64 * 68;       // [64 k][68 pad] transposed
    float* Vs = Kt + 64 * 68;       // [64 key][64 dim]
    float* Ps = Vs + 64 * 64;       // [64 qrow][64 key]

    const int tid = threadIdx.x;
    const int tx = tid & 15, ty = tid >> 4;
    const int qt = blockIdx.x;
    const int h  = blockIdx.y;
    const int b  = blockIdx.z;
    const float scale = 0.125f;     // 1/sqrt(64)

    // Load Q tile (64 rows x 64 dims) -> Qt[d][row], pre-scaled
    #pragma unroll
    for (int q4 = tid; q4 < 1024; q4 += 256) {
        int row = q4 >> 4, d4 = (q4 & 15) * 4;
        const float4 v = *(const float4*)
            &qkv[((size_t)(b * Tt + qt * 64 + row)) * 3072 + h * 64 + d4];
        Qt[(d4 + 0) * 68 + row] = v.x * scale;
        Qt[(d4 + 1) * 68 + row] = v.y * scale;
        Qt[(d4 + 2) * 68 + row] = v.z * scale;
        Qt[(d4 + 3) * 68 + row] = v.w * scale;
    }

    float m[4]  = {-1e30f, -1e30f, -1e30f, -1e30f};
    float l[4]  = {0.f, 0.f, 0.f, 0.f};
    float o[4][4] = {};

    for (int kt = 0; kt <= qt; kt++) {
        __syncthreads();  // previous-iter Kt/Vs/Ps reads done
        // Load K transposed + V natural
        #pragma unroll
        for (int q4 = tid; q4 < 1024; q4 += 256) {
            int row = q4 >> 4, d4 = (q4 & 15) * 4;
            size_t gbase = ((size_t)(b * Tt + kt * 64 + row)) * 3072 + h * 64 + d4;
            float4 kv = *(const float4*)&qkv[gbase + 1024];
            Kt[(d4 + 0) * 68 + row] = kv.x;
            Kt[(d4 + 1) * 68 + row] = kv.y;
            Kt[(d4 + 2) * 68 + row] = kv.z;
            Kt[(d4 + 3) * 68 + row] = kv.w;
            float4 vv = *(const float4*)&qkv[gbase + 2048];
            *(float4*)&Vs[row * 64 + d4] = vv;
        }
        __syncthreads();

        // S = (Q*scale) @ K^T, 4x4 per thread
        float s[4][4] = {};
        #pragma unroll
        for (int kk = 0; kk < 64; kk++) {
            float4 a  = *(const float4*)&Qt[kk * 68 + ty * 4];
            float4 bk = *(const float4*)&Kt[kk * 68 + tx * 4];
            float ar[4] = {a.x, a.y, a.z, a.w};
            float br[4] = {bk.x, bk.y, bk.z, bk.w};
            #pragma unroll
            for (int r = 0; r < 4; r++)
                #pragma unroll
                for (int c = 0; c < 4; c++)
                    s[r][c] += ar[r] * br[c];
        }

        if (kt == qt) {  // causal mask on diagonal tile
            #pragma unroll
            for (int r = 0; r < 4; r++)
                #pragma unroll
                for (int c = 0; c < 4; c++)
                    if (tx * 4 + c > ty * 4 + r) s[r][c] = -1e30f;
        }

        // Online softmax per row (16 threads with same ty share a row group)
        #pragma unroll
        for (int r = 0; r < 4; r++) {
            float tm = fmaxf(fmaxf(s[r][0], s[r][1]), fmaxf(s[r][2], s[r][3]));
            tm = fmaxf(tm, __shfl_xor_sync(0xffffffffu, tm, 8, 16));
            tm = fmaxf(tm, __shfl_xor_sync(0xffffffffu, tm, 4, 16));
            tm = fmaxf(tm, __shfl_xor_sync(0xffffffffu, tm, 2, 16));
            tm = fmaxf(tm, __shfl_xor_sync(0xffffffffu, tm, 1, 16));
            float mn = fmaxf(m[r], tm);
            float fac = __expf(m[r] - mn);
            float sum = 0.f;
            #pragma unroll
            for (int c = 0; c < 4; c++) {
                float p = __expf(s[r][c] - mn);
                s[r][c] = p;
                sum += p;
            }
            sum += __shfl_xor_sync(0xffffffffu, sum, 8, 16);
            sum += __shfl_xor_sync(0xffffffffu, sum, 4, 16);
            sum += __shfl_xor_sync(0xffffffffu, sum, 2, 16);
            sum += __shfl_xor_sync(0xffffffffu, sum, 1, 16);
            l[r] = l[r] * fac + sum;
            m[r] = mn;
            #pragma unroll
            for (int c = 0; c < 4; c++) o[r][c] *= fac;
            *(float4*)&Ps[(ty * 4 + r) * 64 + tx * 4] =
                make_float4(s[r][0], s[r][1], s[r][2], s[r][3]);
        }
        __syncthreads();

        // O += P @ V
        #pragma unroll
        for (int j = 0; j < 64; j++) {
            float4 v = *(const float4*)&Vs[j * 64 + tx * 4];
            #pragma unroll
            for (int r = 0; r < 4; r++) {
                float p = Ps[(ty * 4 + r) * 64 + j];
                o[r][0] += p * v.x;
                o[r][1] += p * v.y;
                o[r][2] += p * v.z;
                o[r][3] += p * v.w;
            }
        }
    }

    // Epilogue: normalize and write to (b, t, h*64+d) layout
    #pragma unroll
    for (int r = 0; r < 4; r++) {
        float inv = 1.0f / l[r];
        float* orow = &out[((size_t)(b * Tt + qt * 64 + ty * 4 + r)) * 1024
                           + h * 64 + tx * 4];
        *(float4*)orow = make_float4(o[r][0] * inv, o[r][1] * inv,
                                     o[r][2] * inv, o[r][3] * inv);
    }
}

// ---------------------------------------------------------------------------
// Launch
// ---------------------------------------------------------------------------
extern "C" void kernel_launch(void* const* d_in, const int* in_sizes, int n_in,
                              void* d_out, int out_size)
{
    const float* x      = (const float*)d_in[0];
    const float* rope   = (const float*)d_in[1];
    const float* W_attn = (const float*)d_in[2];
    const float* W_proj = (const float*)d_in[3];
    // d_in[4] = mask (causal, implemented analytically)
    float* out = (float*)d_out;

    float* qkv;  cudaGetSymbolAddress((void**)&qkv,  g_qkv);
    float* attn; cudaGetSymbolAddress((void**)&attn, g_attn);

    // 1. QKV = x @ W_attn : (4096,1024) @ (1024,3072)
    sgemm128<<<dim3(3 * Dd / 128, M_ROWS / 128), 256>>>(x, W_attn, qkv,
                                                        M_ROWS, 3 * Dd, Dd);

    // 2. RoPE on q,k halves
    {
        int total = Bb * Tt * Hh * 32;   // 2^21
        rope_kernel<<<total / 256, 256>>>(qkv, rope);
    }

    // 3. Causal flash attention
    cudaFuncSetAttribute(attn_kernel,
                         cudaFuncAttributeMaxDynamicSharedMemorySize,
                         ATTN_SMEM_BYTES);
    attn_kernel<<<dim3(Tt / 64, Hh, Bb), 256, ATTN_SMEM_BYTES>>>(qkv, attn);

    // 4. out = attn @ W_proj : (4096,1024) @ (1024,1024)
    sgemm128<<<dim3(Dd / 128, M_ROWS / 128), 256>>>(attn, W_proj, out,
                                                    M_ROWS, Dd, Dd);
}

// round 2
// speedup vs baseline: 2.4722x; 2.4722x over previous
#include <cuda_runtime.h>
#include <cuda_bf16.h>

// Problem constants
#define Bb 2
#define Tt 2048
#define Dd 1024
#define Hh 16
#define HDd 64
#define M_ROWS (Bb * Tt)        // 4096

// Scratch (allocation-free rule: device globals)
__device__ float g_qkv[(size_t)M_ROWS * 3 * Dd];   // (4096, 3072)
__device__ float g_attn[(size_t)M_ROWS * Dd];      // (4096, 1024)

// ---------------------------------------------------------------------------
// Helpers: fp32 -> tf32 conversion and m16n8k8 tf32 MMA
// ---------------------------------------------------------------------------
__device__ __forceinline__ unsigned f2tf32(float f) {
    unsigned u;
    asm("cvt.rna.tf32.f32 %0, %1;" : "=r"(u) : "f"(f));
    return u;
}

__device__ __forceinline__ void mma_tf32(float4& c, const unsigned a[4],
                                         const unsigned b[2]) {
    asm volatile(
        "mma.sync.aligned.m16n8k8.row.col.f32.tf32.tf32.f32 "
        "{%0,%1,%2,%3}, {%4,%5,%6,%7}, {%8,%9}, {%0,%1,%2,%3};\n"
        : "+f"(c.x), "+f"(c.y), "+f"(c.z), "+f"(c.w)
        : "r"(a[0]), "r"(a[1]), "r"(a[2]), "r"(a[3]), "r"(b[0]), "r"(b[1]));
}

// ---------------------------------------------------------------------------
// tf32 GEMM: C[M,N] = A[M,K] @ B[K,N], row-major fp32 in/out.
// 128x128 block, BK=32, 256 threads (8 warps as 2x4), warp tile 64x32.
// ---------------------------------------------------------------------------
__global__ __launch_bounds__(256) void gemm_tf32(
    const float* __restrict__ A, const float* __restrict__ B,
    float* __restrict__ C, int M, int N, int K)
{
    __shared__ unsigned As[32][136];   // [k][m], pad 136 -> bank stride 8
    __shared__ unsigned Bs[32][136];   // [k][n]

    const int tid  = threadIdx.x;
    const int warp = tid >> 5, lane = tid & 31;
    const int g  = lane >> 2;          // groupID 0..7
    const int i4 = lane & 3;           // inGroup 0..3
    const int wm = (warp >> 2) * 64;   // warp row base (2 warp-rows)
    const int wn = (warp & 3) * 32;    // warp col base (4 warp-cols)
    const int brow = blockIdx.y * 128;
    const int bcol = blockIdx.x * 128;

    float4 acc[4][4];
    #pragma unroll
    for (int mt = 0; mt < 4; mt++)
        #pragma unroll
        for (int nt = 0; nt < 4; nt++)
            acc[mt][nt] = make_float4(0.f, 0.f, 0.f, 0.f);

    for (int kt = 0; kt < K; kt += 32) {
        __syncthreads();   // previous compute done before overwriting smem
        #pragma unroll
        for (int r = 0; r < 4; r++) {
            int idx = tid + 256 * r;                 // 0..1023
            int arow = idx >> 3, ac = (idx & 7) * 4; // 128 rows x 8 f4-cols
            float4 av = *(const float4*)&A[(size_t)(brow + arow) * K + kt + ac];
            As[ac + 0][arow] = f2tf32(av.x);
            As[ac + 1][arow] = f2tf32(av.y);
            As[ac + 2][arow] = f2tf32(av.z);
            As[ac + 3][arow] = f2tf32(av.w);
            int bk = idx >> 5, bc = (idx & 31) * 4;  // 32 rows x 32 f4-cols
            float4 bv = *(const float4*)&B[(size_t)(kt + bk) * N + bcol + bc];
            Bs[bk][bc + 0] = f2tf32(bv.x);
            Bs[bk][bc + 1] = f2tf32(bv.y);
            Bs[bk][bc + 2] = f2tf32(bv.z);
            Bs[bk][bc + 3] = f2tf32(bv.w);
        }
        __syncthreads();

        #pragma unroll
        for (int ks = 0; ks < 4; ks++) {
            unsigned af[4][4], bf[4][2];
            #pragma unroll
            for (int mt = 0; mt < 4; mt++) {
                int row = wm + mt * 16 + g;
                af[mt][0] = As[ks * 8 + i4][row];
                af[mt][1] = As[ks * 8 + i4][row + 8];
                af[mt][2] = As[ks * 8 + i4 + 4][row];
                af[mt][3] = As[ks * 8 + i4 + 4][row + 8];
            }
            #pragma unroll
            for (int nt = 0; nt < 4; nt++) {
                int col = wn + nt * 8 + g;
                bf[nt][0] = Bs[ks * 8 + i4][col];
                bf[nt][1] = Bs[ks * 8 + i4 + 4][col];
            }
            #pragma unroll
            for (int mt = 0; mt < 4; mt++)
                #pragma unroll
                for (int nt = 0; nt < 4; nt++)
                    mma_tf32(acc[mt][nt], af[mt], bf[nt]);
        }
    }

    // Epilogue: float2 stores
    #pragma unroll
    for (int mt = 0; mt < 4; mt++) {
        int row = brow + wm + mt * 16 + g;
        #pragma unroll
        for (int nt = 0; nt < 4; nt++) {
            int col = bcol + wn + nt * 8 + i4 * 2;
            *(float2*)&C[(size_t)row * N + col] =
                make_float2(acc[mt][nt].x, acc[mt][nt].y);
            *(float2*)&C[(size_t)(row + 8) * N + col] =
                make_float2(acc[mt][nt].z, acc[mt][nt].w);
        }
    }
}

// ---------------------------------------------------------------------------
// RoPE applied in-place to Q and K halves of the qkv buffer.
// ---------------------------------------------------------------------------
__global__ void rope_kernel(float* __restrict__ qkv, const float* __restrict__ rope)
{
    int idx = blockIdx.x * blockDim.x + threadIdx.x;  // over B*T*H*32
    int i = idx & 31;
    int h = (idx >> 5) & 15;
    int t = (idx >> 9) & (Tt - 1);
    int b = idx >> 20;

    float c = rope[(t * 32 + i) * 2 + 0];
    float s = rope[(t * 32 + i) * 2 + 1];
    size_t base = ((size_t)(b * Tt + t)) * 3072 + h * 64 + 2 * i;

    float x0 = qkv[base], x1 = qkv[base + 1];
    qkv[base]     = x0 * c - x1 * s;
    qkv[base + 1] = x1 * c + x0 * s;

    float y0 = qkv[base + 1024], y1 = qkv[base + 1025];
    qkv[base + 1024] = y0 * c - y1 * s;
    qkv[base + 1025] = y1 * c + y0 * s;
}

// ---------------------------------------------------------------------------
// Flash attention (tf32 MMA): causal, per (b,h,qtile=64). 128 threads (4 warps),
// each warp owns a 16-row slab (m16) across all 64 keys / 64 dims (8 n-tiles).
// P tile round-trips through smem aliased onto the K tile.
// ---------------------------------------------------------------------------
#define AT_ST 72
#define ATTN_SMEM_BYTES (3 * 64 * AT_ST * 4)   // 55296

__global__ __launch_bounds__(128) void attn_tf32(
    const float* __restrict__ qkv, float* __restrict__ out)
{
    extern __shared__ unsigned smu[];
    unsigned* Qs = smu;                 // [64 k(d)][72 m(q)]  (transposed)
    unsigned* Ks = Qs + 64 * AT_ST;     // [64 n(key)][72 k(d)]; aliased as Ps[64 q][72 key]
    unsigned* Vs = Ks + 64 * AT_ST;     // [64 k(key)][72 n(d)]

    const int tid  = threadIdx.x;
    const int warp = tid >> 5, lane = tid & 31;
    const int g  = lane >> 2;
    const int i4 = lane & 3;
    const int qt = gridDim.x - 1 - blockIdx.x;   // big tiles first
    const int h  = blockIdx.y;
    const int b  = blockIdx.z;
    const int r0 = warp * 16 + g;                // local q row (and r0+8)

    const size_t qbase = ((size_t)(b * Tt + qt * 64)) * 3072 + h * 64;

    // Load Q tile transposed, pre-scaled, tf32
    #pragma unroll
    for (int it = 0; it < 8; it++) {
        int idx = tid + 128 * it;                // 0..1023
        int row = idx >> 4, d4 = (idx & 15) * 4;
        float4 v = *(const float4*)&qkv[qbase + (size_t)row * 3072 + d4];
        Qs[(d4 + 0) * AT_ST + row] = f2tf32(v.x * 0.125f);
        Qs[(d4 + 1) * AT_ST + row] = f2tf32(v.y * 0.125f);
        Qs[(d4 + 2) * AT_ST + row] = f2tf32(v.z * 0.125f);
        Qs[(d4 + 3) * AT_ST + row] = f2tf32(v.w * 0.125f);
    }

    float m0 = -1e30f, m1 = -1e30f, l0 = 0.f, l1 = 0.f;
    float4 o[8];
    #pragma unroll
    for (int nt = 0; nt < 8; nt++) o[nt] = make_float4(0.f, 0.f, 0.f, 0.f);

    for (int kt = 0; kt <= qt; kt++) {
        __syncthreads();   // prev iter's Ps/Vs reads done (and Qs ready on kt=0)
        const size_t kbase = ((size_t)(b * Tt + kt * 64)) * 3072 + h * 64;
        #pragma unroll
        for (int it = 0; it < 8; it++) {
            int idx = tid + 128 * it;
            int row = idx >> 4, d4 = (idx & 15) * 4;
            float4 kv = *(const float4*)&qkv[kbase + (size_t)row * 3072 + 1024 + d4];
            Ks[row * AT_ST + d4 + 0] = f2tf32(kv.x);
            Ks[row * AT_ST + d4 + 1] = f2tf32(kv.y);
            Ks[row * AT_ST + d4 + 2] = f2tf32(kv.z);
            Ks[row * AT_ST + d4 + 3] = f2tf32(kv.w);
            float4 vv = *(const float4*)&qkv[kbase + (size_t)row * 3072 + 2048 + d4];
            Vs[row * AT_ST + d4 + 0] = f2tf32(vv.x);
            Vs[row * AT_ST + d4 + 1] = f2tf32(vv.y);
            Vs[row * AT_ST + d4 + 2] = f2tf32(vv.z);
            Vs[row * AT_ST + d4 + 3] = f2tf32(vv.w);
        }
        __syncthreads();

        // S = Q @ K^T   (A from Qs[k][m], B from Ks[n][k] = col-major)
        float4 s[8];
        #pragma unroll
        for (int nt = 0; nt < 8; nt++) s[nt] = make_float4(0.f, 0.f, 0.f, 0.f);
        #pragma unroll
        for (int ks = 0; ks < 8; ks++) {
            unsigned af[4];
            af[0] = Qs[(ks * 8 + i4) * AT_ST + r0];
            af[1] = Qs[(ks * 8 + i4) * AT_ST + r0 + 8];
            af[2] = Qs[(ks * 8 + i4 + 4) * AT_ST + r0];
            af[3] = Qs[(ks * 8 + i4 + 4) * AT_ST + r0 + 8];
            #pragma unroll
            for (int nt = 0; nt < 8; nt++) {
                unsigned bf[2];
                int key = nt * 8 + g;
                bf[0] = Ks[key * AT_ST + ks * 8 + i4];
                bf[1] = Ks[key * AT_ST + ks * 8 + i4 + 4];
                mma_tf32(s[nt], af, bf);
            }
        }

        if (kt == qt) {   // causal mask on diagonal tile
            #pragma unroll
            for (int nt = 0; nt < 8; nt++) {
                int c0 = nt * 8 + i4 * 2;
                if (c0     > r0)     s[nt].x = -1e30f;
                if (c0 + 1 > r0)     s[nt].y = -1e30f;
                if (c0     > r0 + 8) s[nt].z = -1e30f;
                if (c0 + 1 > r0 + 8) s[nt].w = -1e30f;
            }
        }

        // Online softmax (rows r0 and r0+8, spread over 4 lanes with same g)
        float mx0 = -1e30f, mx1 = -1e30f;
        #pragma unroll
        for (int nt = 0; nt < 8; nt++) {
            mx0 = fmaxf(mx0, fmaxf(s[nt].x, s[nt].y));
            mx1 = fmaxf(mx1, fmaxf(s[nt].z, s[nt].w));
        }
        mx0 = fmaxf(mx0, __shfl_xor_sync(0xffffffffu, mx0, 1));
        mx0 = fmaxf(mx0, __shfl_xor_sync(0xffffffffu, mx0, 2));
        mx1 = fmaxf(mx1, __shfl_xor_sync(0xffffffffu, mx1, 1));
        mx1 = fmaxf(mx1, __shfl_xor_sync(0xffffffffu, mx1, 2));
        float nm0 = fmaxf(m0, mx0), nm1 = fmaxf(m1, mx1);
        float f0 = __expf(m0 - nm0), f1 = __expf(m1 - nm1);
        float sum0 = 0.f, sum1 = 0.f;
        #pragma unroll
        for (int nt = 0; nt < 8; nt++) {
            s[nt].x = __expf(s[nt].x - nm0);
            s[nt].y = __expf(s[nt].y - nm0);
            s[nt].z = __expf(s[nt].z - nm1);
            s[nt].w = __expf(s[nt].w - nm1);
            sum0 += s[nt].x + s[nt].y;
            sum1 += s[nt].z + s[nt].w;
        }
        sum0 += __shfl_xor_sync(0xffffffffu, sum0, 1);
        sum0 += __shfl_xor_sync(0xffffffffu, sum0, 2);
        sum1 += __shfl_xor_sync(0xffffffffu, sum1, 1);
        sum1 += __shfl_xor_sync(0xffffffffu, sum1, 2);
        l0 = l0 * f0 + sum0;  m0 = nm0;
        l1 = l1 * f1 + sum1;  m1 = nm1;
        #pragma unroll
        for (int nt = 0; nt < 8; nt++) {
            o[nt].x *= f0; o[nt].y *= f0;
            o[nt].z *= f1; o[nt].w *= f1;
        }

        __syncthreads();   // all warps' Ks reads done before overwriting with Ps
        unsigned* Ps = Ks;
        #pragma unroll
        for (int nt = 0; nt < 8; nt++) {
            int c0 = nt * 8 + i4 * 2;
            Ps[r0 * AT_ST + c0]           = f2tf32(s[nt].x);
            Ps[r0 * AT_ST + c0 + 1]       = f2tf32(s[nt].y);
            Ps[(r0 + 8) * AT_ST + c0]     = f2tf32(s[nt].z);
            Ps[(r0 + 8) * AT_ST + c0 + 1] = f2tf32(s[nt].w);
        }
        __syncwarp();      // P rows are private to this warp; warp-scope is enough

        // O += P @ V   (A from Ps[m][k(key)], B from Vs[k(key)][n(d)] col-major)
        #pragma unroll
        for (int ks = 0; ks < 8; ks++) {
            unsigned af[4];
            af[0] = Ps[r0 * AT_ST + ks * 8 + i4];
            af[1] = Ps[(r0 + 8) * AT_ST + ks * 8 + i4];
            af[2] = Ps[r0 * AT_ST + ks * 8 + i4 + 4];
            af[3] = Ps[(r0 + 8) * AT_ST + ks * 8 + i4 + 4];
            #pragma unroll
            for (int nt = 0; nt < 8; nt++) {
                unsigned bf[2];
                bf[0] = Vs[(ks * 8 + i4) * AT_ST + nt * 8 + g];
                bf[1] = Vs[(ks * 8 + i4 + 4) * AT_ST + nt * 8 + g];
                mma_tf32(o[nt], af, bf);
            }
        }
    }

    // Epilogue: normalize and write (b, t, h*64 + d)
    float inv0 = 1.0f / l0, inv1 = 1.0f / l1;
    size_t obase = ((size_t)(b * Tt + qt * 64)) * 1024 + h * 64;
    #pragma unroll
    for (int nt = 0; nt < 8; nt++) {
        int c0 = nt * 8 + i4 * 2;
        *(float2*)&out[obase + (size_t)r0 * 1024 + c0] =
            make_float2(o[nt].x * inv0, o[nt].y * inv0);
        *(float2*)&out[obase + (size_t)(r0 + 8) * 1024 + c0] =
            make_float2(o[nt].z * inv1, o[nt].w * inv1);
    }
}

// ---------------------------------------------------------------------------
// Launch
// ---------------------------------------------------------------------------
extern "C" void kernel_launch(void* const* d_in, const int* in_sizes, int n_in,
                              void* d_out, int out_size)
{
    const float* x      = (const float*)d_in[0];
    const float* rope   = (const float*)d_in[1];
    const float* W_attn = (const float*)d_in[2];
    const float* W_proj = (const float*)d_in[3];
    float* out = (float*)d_out;

    float* qkv;  cudaGetSymbolAddress((void**)&qkv,  g_qkv);
    float* attn; cudaGetSymbolAddress((void**)&attn, g_attn);

    // 1. QKV = x @ W_attn : (4096,1024) @ (1024,3072)
    gemm_tf32<<<dim3(3 * Dd / 128, M_ROWS / 128), 256>>>(x, W_attn, qkv,
                                                         M_ROWS, 3 * Dd, Dd);

    // 2. RoPE on q,k halves
    rope_kernel<<<(Bb * Tt * Hh * 32) / 256, 256>>>(qkv, rope);

    // 3. Causal flash attention (tf32 MMA)
    cudaFuncSetAttribute(attn_tf32,
                         cudaFuncAttributeMaxDynamicSharedMemorySize,
                         ATTN_SMEM_BYTES);
    attn_tf32<<<dim3(Tt / 64, Hh, Bb), 128, ATTN_SMEM_BYTES>>>(qkv, attn);

    // 4. out = attn @ W_proj : (4096,1024) @ (1024,1024)
    gemm_tf32<<<dim3(Dd / 128, M_ROWS / 128), 256>>>(attn, W_proj, out,
                                                     M_ROWS, Dd, Dd);
}

// round 4
// speedup vs baseline: 3.1078x; 1.2571x over previous
#include <cuda_runtime.h>
#include <cuda_bf16.h>

// Problem constants (constexpr: no macro-collision hazard)
constexpr int kB = 2;
constexpr int kT = 2048;
constexpr int kD = 1024;
constexpr int kH = 16;
constexpr int kM = kB * kT;   // 4096 rows

// Scratch (allocation-free rule: device globals)
__device__ float g_qkv[(size_t)kM * 3 * kD];   // (4096, 3072)
__device__ float g_attn[(size_t)kM * kD];      // (4096, 1024)

// ---------------------------------------------------------------------------
// Helpers
// ---------------------------------------------------------------------------
__device__ __forceinline__ unsigned f2tf32(float f) {
    unsigned u;
    asm("cvt.rna.tf32.f32 %0, %1;" : "=r"(u) : "f"(f));
    return u;
}

__device__ __forceinline__ void mma_tf32(float4& c, const unsigned a[4],
                                         const unsigned b[2]) {
    asm volatile(
        "mma.sync.aligned.m16n8k8.row.col.f32.tf32.tf32.f32 "
        "{%0,%1,%2,%3}, {%4,%5,%6,%7}, {%8,%9}, {%0,%1,%2,%3};\n"
        : "+f"(c.x), "+f"(c.y), "+f"(c.z), "+f"(c.w)
        : "r"(a[0]), "r"(a[1]), "r"(a[2]), "r"(a[3]), "r"(b[0]), "r"(b[1]));
}

__device__ __forceinline__ unsigned sptr(const void* p) {
    return (unsigned)__cvta_generic_to_shared(p);
}

#define CP_ASYNC16(dst, src) \
    asm volatile("cp.async.cg.shared.global [%0], [%1], 16;" :: "r"(dst), "l"(src))

// ---------------------------------------------------------------------------
// tf32 GEMM: C[M,N] = A[M,K] @ B[K,N], row-major fp32.
// 128x128 CTA, BK=32, 128 threads (4 warps, 2x2), warp tile 64x64.
// Double-buffered smem via cp.async.
// ---------------------------------------------------------------------------
constexpr int GA_ST = 36;    // A smem row stride (words)
constexpr int GB_ST = 136;   // B smem row stride (words)
constexpr int GEMM_SMEM = (2 * 128 * GA_ST + 2 * 32 * GB_ST) * 4;  // 71680 B

__global__ __launch_bounds__(128, 2) void gemm_tf32(
    const float* __restrict__ A, const float* __restrict__ B,
    float* __restrict__ C, int M, int N, int K)
{
    extern __shared__ float gsh[];
    float* As = gsh;                       // [2][128][GA_ST]
    float* Bs = gsh + 2 * 128 * GA_ST;     // [2][32][GB_ST]

    const int tid  = threadIdx.x;
    const int warp = tid >> 5, lane = tid & 31;
    const int g  = lane >> 2;
    const int i4 = lane & 3;
    const int wm = (warp >> 1) * 64;
    const int wn = (warp & 1) * 64;
    const int brow = blockIdx.y * 128;
    const int bcol = blockIdx.x * 128;

    float4 acc[4][8];
    #pragma unroll
    for (int mt = 0; mt < 4; mt++)
        #pragma unroll
        for (int nt = 0; nt < 8; nt++)
            acc[mt][nt] = make_float4(0.f, 0.f, 0.f, 0.f);

    const int NIT = K >> 5;   // K/32

    auto stage = [&](int kt, int buf) {
        float* a_dst = As + buf * 128 * GA_ST;
        float* b_dst = Bs + buf * 32 * GB_ST;
        #pragma unroll
        for (int i = 0; i < 8; i++) {
            int id = tid + 128 * i;           // 0..1023
            int r = id >> 3, c4 = (id & 7) * 4;
            CP_ASYNC16(sptr(&a_dst[r * GA_ST + c4]),
                       &A[(size_t)(brow + r) * K + kt + c4]);
        }
        #pragma unroll
        for (int i = 0; i < 8; i++) {
            int id = tid + 128 * i;
            int k = id >> 5, n4 = (id & 31) * 4;
            CP_ASYNC16(sptr(&b_dst[k * GB_ST + n4]),
                       &B[(size_t)(kt + k) * N + bcol + n4]);
        }
    };

    stage(0, 0);
    asm volatile("cp.async.commit_group;");

    int buf = 0;
    #pragma unroll 1
    for (int it = 0; it < NIT; it++) {
        if (it + 1 < NIT) {
            stage((it + 1) << 5, buf ^ 1);
            asm volatile("cp.async.commit_group;");
            asm volatile("cp.async.wait_group 1;");
        } else {
            asm volatile("cp.async.wait_group 0;");
        }
        __syncthreads();

        const float* a_src = As + buf * 128 * GA_ST;
        const float* b_src = Bs + buf * 32 * GB_ST;

        #pragma unroll
        for (int ks = 0; ks < 4; ks++) {
            unsigned af[4][4], bf[8][2];
            #pragma unroll
            for (int mt = 0; mt < 4; mt++) {
                const float* ap = &a_src[(wm + mt * 16 + g) * GA_ST + ks * 8 + i4];
                af[mt][0] = f2tf32(ap[0]);
                af[mt][1] = f2tf32(ap[8 * GA_ST]);
                af[mt][2] = f2tf32(ap[4]);
                af[mt][3] = f2tf32(ap[8 * GA_ST + 4]);
            }
            #pragma unroll
            for (int nt = 0; nt < 8; nt++) {
                const float* bp = &b_src[(ks * 8 + i4) * GB_ST + wn + nt * 8 + g];
                bf[nt][0] = f2tf32(bp[0]);
                bf[nt][1] = f2tf32(bp[4 * GB_ST]);
            }
            #pragma unroll
            for (int mt = 0; mt < 4; mt++)
                #pragma unroll
                for (int nt = 0; nt < 8; nt++)
                    mma_tf32(acc[mt][nt], af[mt], bf[nt]);
        }
        __syncthreads();   // all warps done with buf before restaging
        buf ^= 1;
    }

    // Epilogue
    #pragma unroll
    for (int mt = 0; mt < 4; mt++) {
        int row = brow + wm + mt * 16 + g;
        #pragma unroll
        for (int nt = 0; nt < 8; nt++) {
            int col = bcol + wn + nt * 8 + i4 * 2;
            *(float2*)&C[(size_t)row * N + col] =
                make_float2(acc[mt][nt].x, acc[mt][nt].y);
            *(float2*)&C[(size_t)(row + 8) * N + col] =
                make_float2(acc[mt][nt].z, acc[mt][nt].w);
        }
    }
}

// ---------------------------------------------------------------------------
// Flash attention, tf32 MMA, RoPE fused into Q/K loads.
// BM=128 (4 warps x m32), BN=64, HD=64, causal. 128 threads.
// ---------------------------------------------------------------------------
constexpr int AQ_ST = 136;  // Qs [d][m]
constexpr int AK_ST = 72;   // Ks [key][d]
constexpr int AV_ST = 72;   // Vs [key][d]
constexpr int AP_ST = 68;   // Ps [m][key]
constexpr int ATTN_SMEM =
    (64 * AQ_ST + 64 * AK_ST + 64 * AV_ST + 128 * AP_ST) * 4;  // 106496 B

__global__ __launch_bounds__(128, 2) void attn_tf32(
    const float* __restrict__ qkv, const float* __restrict__ rope,
    float* __restrict__ out)
{
    extern __shared__ unsigned ash[];
    unsigned* Qs = ash;                  // [64 d][AQ_ST m] (transposed, scaled, roped)
    unsigned* Ks = Qs + 64 * AQ_ST;      // [64 key][AK_ST d] (roped)
    unsigned* Vs = Ks + 64 * AK_ST;      // [64 key][AV_ST d]
    unsigned* Ps = Vs + 64 * AV_ST;      // [128 m][AP_ST key] (warp-private rows)

    const int tid  = threadIdx.x;
    const int warp = tid >> 5, lane = tid & 31;
    const int g  = lane >> 2;
    const int i4 = lane & 3;
    const int qt = gridDim.x - 1 - blockIdx.x;   // big tiles first
    const int h  = blockIdx.y;
    const int b  = blockIdx.z;

    // ---- Load Q tile (128 rows x 64 dims), RoPE + scale, transposed ----
    #pragma unroll
    for (int i = 0; i < 16; i++) {
        int id  = tid + 128 * i;          // 0..2047
        int row = id & 127;
        int d4  = (id >> 7) * 4;
        int t   = qt * 128 + row;
        float4 v = *(const float4*)
            &qkv[((size_t)(b * kT + t)) * 3072 + h * 64 + d4];
        int p0 = d4 >> 1;
        float c0 = rope[(t * 32 + p0) * 2],     s0 = rope[(t * 32 + p0) * 2 + 1];
        float c1 = rope[(t * 32 + p0 + 1) * 2], s1 = rope[(t * 32 + p0 + 1) * 2 + 1];
        float q0 = v.x * c0 - v.y * s0, q1 = v.y * c0 + v.x * s0;
        float q2 = v.z * c1 - v.w * s1, q3 = v.w * c1 + v.z * s1;
        Qs[(d4 + 0) * AQ_ST + row] = f2tf32(q0 * 0.125f);
        Qs[(d4 + 1) * AQ_ST + row] = f2tf32(q1 * 0.125f);
        Qs[(d4 + 2) * AQ_ST + row] = f2tf32(q2 * 0.125f);
        Qs[(d4 + 3) * AQ_ST + row] = f2tf32(q3 * 0.125f);
    }

    float m[2][2], l[2][2];
    #pragma unroll
    for (int mt = 0; mt < 2; mt++) {
        m[mt][0] = m[mt][1] = -1e30f;
        l[mt][0] = l[mt][1] = 0.f;
    }
    float4 o[2][8];
    #pragma unroll
    for (int mt = 0; mt < 2; mt++)
        #pragma unroll
        for (int nt = 0; nt < 8; nt++)
            o[mt][nt] = make_float4(0.f, 0.f, 0.f, 0.f);

    const int nkt = 2 * qt + 2;
    for (int kt = 0; kt < nkt; kt++) {
        __syncthreads();   // previous PV reads of Ks/Vs done
        // ---- Load K (roped) and V tiles: 64 rows x 64 dims each ----
        #pragma unroll
        for (int i = 0; i < 8; i++) {
            int id  = tid + 128 * i;      // 0..1023
            int row = id >> 4;
            int d4  = (id & 15) * 4;
            int t   = kt * 64 + row;
            size_t gb = ((size_t)(b * kT + t)) * 3072 + h * 64 + d4;
            float4 kv = *(const float4*)&qkv[gb + 1024];
            int p0 = d4 >> 1;
            float c0 = rope[(t * 32 + p0) * 2],     s0 = rope[(t * 32 + p0) * 2 + 1];
            float c1 = rope[(t * 32 + p0 + 1) * 2], s1 = rope[(t * 32 + p0 + 1) * 2 + 1];
            uint4 kk;
            kk.x = f2tf32(kv.x * c0 - kv.y * s0);
            kk.y = f2tf32(kv.y * c0 + kv.x * s0);
            kk.z = f2tf32(kv.z * c1 - kv.w * s1);
            kk.w = f2tf32(kv.w * c1 + kv.z * s1);
            *(uint4*)&Ks[row * AK_ST + d4] = kk;
            float4 vv = *(const float4*)&qkv[gb + 2048];
            uint4 vu;
            vu.x = f2tf32(vv.x); vu.y = f2tf32(vv.y);
            vu.z = f2tf32(vv.z); vu.w = f2tf32(vv.w);
            *(uint4*)&Vs[row * AV_ST + d4] = vu;
        }
        __syncthreads();

        // Warps whose rows are entirely left of this key tile skip compute.
        if (kt * 64 <= qt * 128 + warp * 32 + 31) {
            // ---- S = Q @ K^T ----
            float4 s[2][8];
            #pragma unroll
            for (int mt = 0; mt < 2; mt++)
                #pragma unroll
                for (int nt = 0; nt < 8; nt++)
                    s[mt][nt] = make_float4(0.f, 0.f, 0.f, 0.f);

            #pragma unroll
            for (int ks = 0; ks < 8; ks++) {
                unsigned af[2][4];
                #pragma unroll
                for (int mt = 0; mt < 2; mt++) {
                    int r = warp * 32 + mt * 16 + g;
                    af[mt][0] = Qs[(ks * 8 + i4) * AQ_ST + r];
                    af[mt][1] = Qs[(ks * 8 + i4) * AQ_ST + r + 8];
                    af[mt][2] = Qs[(ks * 8 + i4 + 4) * AQ_ST + r];
                    af[mt][3] = Qs[(ks * 8 + i4 + 4) * AQ_ST + r + 8];
                }
                #pragma unroll
                for (int nt = 0; nt < 8; nt++) {
                    unsigned bf[2];
                    int key = nt * 8 + g;
                    bf[0] = Ks[key * AK_ST + ks * 8 + i4];
                    bf[1] = Ks[key * AK_ST + ks * 8 + i4 + 4];
                    mma_tf32(s[0][nt], af[0], bf);
                    mma_tf32(s[1][nt], af[1], bf);
                }
            }

            // ---- Causal mask (only tiles crossing the diagonal) ----
            if (kt >= 2 * qt) {
                #pragma unroll
                for (int mt = 0; mt < 2; mt++) {
                    int r0 = qt * 128 + warp * 32 + mt * 16 + g;
                    #pragma unroll
                    for (int nt = 0; nt < 8; nt++) {
                        int c0 = kt * 64 + nt * 8 + i4 * 2;
                        if (c0     > r0)     s[mt][nt].x = -1e30f;
                        if (c0 + 1 > r0)     s[mt][nt].y = -1e30f;
                        if (c0     > r0 + 8) s[mt][nt].z = -1e30f;
                        if (c0 + 1 > r0 + 8) s[mt][nt].w = -1e30f;
                    }
                }
            }

            // ---- Online softmax + P store (warp-private rows of Ps) ----
            #pragma unroll
            for (int mt = 0; mt < 2; mt++) {
                float mx0 = -1e30f, mx1 = -1e30f;
                #pragma unroll
                for (int nt = 0; nt < 8; nt++) {
                    mx0 = fmaxf(mx0, fmaxf(s[mt][nt].x, s[mt][nt].y));
                    mx1 = fmaxf(mx1, fmaxf(s[mt][nt].z, s[mt][nt].w));
                }
                mx0 = fmaxf(mx0, __shfl_xor_sync(0xffffffffu, mx0, 1));
                mx0 = fmaxf(mx0, __shfl_xor_sync(0xffffffffu, mx0, 2));
                mx1 = fmaxf(mx1, __shfl_xor_sync(0xffffffffu, mx1, 1));
                mx1 = fmaxf(mx1, __shfl_xor_sync(0xffffffffu, mx1, 2));
                float nm0 = fmaxf(m[mt][0], mx0), nm1 = fmaxf(m[mt][1], mx1);
                float f0 = __expf(m[mt][0] - nm0), f1 = __expf(m[mt][1] - nm1);
                float sum0 = 0.f, sum1 = 0.f;
                int r = warp * 32 + mt * 16 + g;
                #pragma unroll
                for (int nt = 0; nt < 8; nt++) {
                    float px = __expf(s[mt][nt].x - nm0);
                    float py = __expf(s[mt][nt].y - nm0);
                    float pz = __expf(s[mt][nt].z - nm1);
                    float pw = __expf(s[mt][nt].w - nm1);
                    sum0 += px + py;
                    sum1 += pz + pw;
                    uint2 lo = make_uint2(f2tf32(px), f2tf32(py));
                    uint2 hi = make_uint2(f2tf32(pz), f2tf32(pw));
                    *(uint2*)&Ps[r * AP_ST + nt * 8 + i4 * 2] = lo;
                    *(uint2*)&Ps[(r + 8) * AP_ST + nt * 8 + i4 * 2] = hi;
                }
                sum0 += __shfl_xor_sync(0xffffffffu, sum0, 1);
                sum0 += __shfl_xor_sync(0xffffffffu, sum0, 2);
                sum1 += __shfl_xor_sync(0xffffffffu, sum1, 1);
                sum1 += __shfl_xor_sync(0xffffffffu, sum1, 2);
                l[mt][0] = l[mt][0] * f0 + sum0;  m[mt][0] = nm0;
                l[mt][1] = l[mt][1] * f1 + sum1;  m[mt][1] = nm1;
                #pragma unroll
                for (int nt = 0; nt < 8; nt++) {
                    o[mt][nt].x *= f0; o[mt][nt].y *= f0;
                    o[mt][nt].z *= f1; o[mt][nt].w *= f1;
                }
            }
            __syncwarp();   // Ps rows are warp-private

            // ---- O += P @ V ----
            #pragma unroll
            for (int ks = 0; ks < 8; ks++) {
                unsigned af[2][4];
                #pragma unroll
                for (int mt = 0; mt < 2; mt++) {
                    int r = warp * 32 + mt * 16 + g;
                    af[mt][0] = Ps[r * AP_ST + ks * 8 + i4];
                    af[mt][1] = Ps[(r + 8) * AP_ST + ks * 8 + i4];
                    af[mt][2] = Ps[r * AP_ST + ks * 8 + i4 + 4];
                    af[mt][3] = Ps[(r + 8) * AP_ST + ks * 8 + i4 + 4];
                }
                #pragma unroll
                for (int nt = 0; nt < 8; nt++) {
                    unsigned bf[2];
                    bf[0] = Vs[(ks * 8 + i4) * AV_ST + nt * 8 + g];
                    bf[1] = Vs[(ks * 8 + i4 + 4) * AV_ST + nt * 8 + g];
                    mma_tf32(o[0][nt], af[0], bf);
                    mma_tf32(o[1][nt], af[1], bf);
                }
            }
        }
    }

    // ---- Epilogue ----
    #pragma unroll
    for (int mt = 0; mt < 2; mt++) {
        float inv0 = 1.0f / l[mt][0], inv1 = 1.0f / l[mt][1];
        int r = qt * 128 + warp * 32 + mt * 16 + g;
        #pragma unroll
        for (int nt = 0; nt < 8; nt++) {
            int col = h * 64 + nt * 8 + i4 * 2;
            *(float2*)&out[((size_t)(b * kT + r)) * 1024 + col] =
                make_float2(o[mt][nt].x * inv0, o[mt][nt].y * inv0);
            *(float2*)&out[((size_t)(b * kT + r + 8)) * 1024 + col] =
                make_float2(o[mt][nt].z * inv1, o[mt][nt].w * inv1);
        }
    }
}

// ---------------------------------------------------------------------------
// Launch
// ---------------------------------------------------------------------------
extern "C" void kernel_launch(void* const* d_in, const int* in_sizes, int n_in,
                              void* d_out, int out_size)
{
    const float* x      = (const float*)d_in[0];
    const float* rope   = (const float*)d_in[1];
    const float* W_attn = (const float*)d_in[2];
    const float* W_proj = (const float*)d_in[3];
    float* out = (float*)d_out;

    float* qkv;  cudaGetSymbolAddress((void**)&qkv,  g_qkv);
    float* attn; cudaGetSymbolAddress((void**)&attn, g_attn);

    cudaFuncSetAttribute(gemm_tf32,
                         cudaFuncAttributeMaxDynamicSharedMemorySize, GEMM_SMEM);
    cudaFuncSetAttribute(attn_tf32,
                         cudaFuncAttributeMaxDynamicSharedMemorySize, ATTN_SMEM);

    // 1. QKV = x @ W_attn : (4096,1024) @ (1024,3072)
    gemm_tf32<<<dim3(3 * kD / 128, kM / 128), 128, GEMM_SMEM>>>(
        x, W_attn, qkv, kM, 3 * kD, kD);

    // 2. Causal flash attention (RoPE fused into Q/K loads)
    attn_tf32<<<dim3(kT / 128, kH, kB), 128, ATTN_SMEM>>>(qkv, rope, attn);

    // 3. out = attn @ W_proj : (4096,1024) @ (1024,1024)
    gemm_tf32<<<dim3(kD / 128, kM / 128), 128, GEMM_SMEM>>>(
        attn, W_proj, out, kM, kD, kD);
}